// round 2
// baseline (speedup 1.0000x reference)
#include <cuda_runtime.h>

#define BB 32
#define IN_C 512
#define HW 4096
#define CODE 256
#define NCLASSES 4
#define MEMN 20
#define DECAYF 0.9f
#define EPSF 1e-12f
#define NTILES 32          // HW / 128 n-tiles in the GEMM

typedef unsigned long long ull;

// Deterministic scratch (no atomics anywhere).
__device__ float g_partial[BB * CODE * NTILES];   // per-(b,o,ntile) masked partial sums
__device__ float g_queue[NCLASSES * MEMN * CODE]; // updated queue state

// ---- f32x2 packed helpers (sm_100+ PTX) ------------------------------------
__device__ __forceinline__ ull pk2(float lo, float hi) {
    ull r; asm("mov.b64 %0, {%1,%2};" : "=l"(r) : "f"(lo), "f"(hi)); return r;
}
__device__ __forceinline__ float2 unpk2(ull v) {
    float2 f; asm("mov.b64 {%0,%1}, %2;" : "=f"(f.x), "=f"(f.y) : "l"(v)); return f;
}
__device__ __forceinline__ ull fma2(ull a, ull b, ull c) {
    ull d; asm("fma.rn.f32x2 %0, %1, %2, %3;" : "=l"(d) : "l"(a), "l"(b), "l"(c)); return d;
}

// labels may be int32 or int64 depending on jax x64 config; detect on device.
// int64 little-endian small values => every odd 32-bit word is zero.
__device__ __forceinline__ int get_label(const int* lab, int i) {
    bool odd_zero = true;
#pragma unroll
    for (int k = 1; k < 32; k += 2) odd_zero &= (lab[k] == 0);
    return odd_zero ? lab[2 * i] : lab[i];
}

// ---------------------------------------------------------------------------
// Kernel 1: batched 1x1-conv GEMM. Per batch: [256 x 512] @ [512 x 4096] + bias.
// Writes x into out channels [256, 512). Also emits per-block masked partials.
// Tiling: 128(o) x 128(n) x 16(k), 256 threads, 8x8 microtile.
// - A tile stored as duplicated f32x2 pairs (broadcast loads, no per-kk packing)
// - B tile: each thread owns n = tx*4 and 64+tx*4 -> 16B phase stride,
//   conflict-free LDS.128 / STS.128
// - inner product via fma.rn.f32x2 (32 FMA2 per kk instead of 64 FFMA)
// ---------------------------------------------------------------------------
__global__ __launch_bounds__(256, 2) void gemm_proj_kernel(
    const float* __restrict__ feats, const float* __restrict__ preds,
    const float* __restrict__ Wp, const float* __restrict__ bp,
    float* __restrict__ out)
{
    const int nt = blockIdx.x;            // n tile (0..31)
    const int ot = blockIdx.y;            // o tile (0..1)
    const int b  = blockIdx.z;
    const int n0 = nt * 128;
    const int o0 = ot * 128;
    const int t  = threadIdx.x;
    const int tx = t & 15;                // n-direction
    const int ty = t >> 4;                // o-direction (8 rows each)

    __shared__ ull   As2[16][128];        // As2[k][o] = dup pair (w,w)   16 KB
    __shared__ float Bs[16][128];         // Bs[k][n]                      8 KB

    ull acc2[8][4];
#pragma unroll
    for (int i = 0; i < 8; i++)
#pragma unroll
        for (int j = 0; j < 4; j++) acc2[i][j] = 0ULL;

    const float* fb = feats + (long long)b * IN_C * HW;

    const int ar = t >> 1;                // 0..127  (Wp row within tile)
    const int ac = (t & 1) * 8;           // 0 or 8  (k offset)
    const int br = t >> 4;                // 0..15   (k row)

    for (int k0 = 0; k0 < IN_C; k0 += 16) {
        float4 av0 = *(const float4*)(Wp + (long long)(o0 + ar) * IN_C + k0 + ac);
        float4 av1 = *(const float4*)(Wp + (long long)(o0 + ar) * IN_C + k0 + ac + 4);
        float4 bv0 = *(const float4*)(fb + (long long)(k0 + br) * HW + n0 + tx * 4);
        float4 bv1 = *(const float4*)(fb + (long long)(k0 + br) * HW + n0 + 64 + tx * 4);
        __syncthreads();
        As2[ac + 0][ar] = pk2(av0.x, av0.x);
        As2[ac + 1][ar] = pk2(av0.y, av0.y);
        As2[ac + 2][ar] = pk2(av0.z, av0.z);
        As2[ac + 3][ar] = pk2(av0.w, av0.w);
        As2[ac + 4][ar] = pk2(av1.x, av1.x);
        As2[ac + 5][ar] = pk2(av1.y, av1.y);
        As2[ac + 6][ar] = pk2(av1.z, av1.z);
        As2[ac + 7][ar] = pk2(av1.w, av1.w);
        *(float4*)&Bs[br][tx * 4]      = bv0;
        *(float4*)&Bs[br][64 + tx * 4] = bv1;
        __syncthreads();
#pragma unroll
        for (int kk = 0; kk < 16; kk++) {
            ull ad[8];
            const ulonglong2* ap = (const ulonglong2*)&As2[kk][ty * 8];
#pragma unroll
            for (int q = 0; q < 4; q++) {
                ulonglong2 v = ap[q];
                ad[2 * q] = v.x; ad[2 * q + 1] = v.y;
            }
            float4 bv0i = *(const float4*)&Bs[kk][tx * 4];
            float4 bv1i = *(const float4*)&Bs[kk][64 + tx * 4];
            ull bq[4];
            bq[0] = pk2(bv0i.x, bv0i.y); bq[1] = pk2(bv0i.z, bv0i.w);
            bq[2] = pk2(bv1i.x, bv1i.y); bq[3] = pk2(bv1i.z, bv1i.w);
#pragma unroll
            for (int i = 0; i < 8; i++)
#pragma unroll
                for (int j = 0; j < 4; j++)
                    acc2[i][j] = fma2(ad[i], bq[j], acc2[i][j]);
        }
    }

    // Epilogue: bias, write x to out[b, 256+o, n], masked partial per o-row.
    float4 pv0 = *(const float4*)(preds + (long long)b * HW + n0 + tx * 4);
    float4 pv1 = *(const float4*)(preds + (long long)b * HW + n0 + 64 + tx * 4);

    float* ob = out + ((long long)b * 2 * CODE + CODE + o0) * HW;

#pragma unroll
    for (int i = 0; i < 8; i++) {
        const int orow = ty * 8 + i;
        const float bias = bp[o0 + orow];
        float2 p0 = unpk2(acc2[i][0]), p1 = unpk2(acc2[i][1]);
        float2 p2 = unpk2(acc2[i][2]), p3 = unpk2(acc2[i][3]);
        float4 v0 = make_float4(p0.x + bias, p0.y + bias, p1.x + bias, p1.y + bias);
        float4 v1 = make_float4(p2.x + bias, p2.y + bias, p3.x + bias, p3.y + bias);
        float rsum = v0.x * pv0.x + v0.y * pv0.y + v0.z * pv0.z + v0.w * pv0.w
                   + v1.x * pv1.x + v1.y * pv1.y + v1.z * pv1.z + v1.w * pv1.w;
        *(float4*)(ob + (long long)orow * HW + n0 + tx * 4)      = v0;
        *(float4*)(ob + (long long)orow * HW + n0 + 64 + tx * 4) = v1;
        // reduce across the 16 tx lanes (same ty occupies a 16-lane half-warp)
#pragma unroll
        for (int off = 1; off < 16; off <<= 1)
            rsum += __shfl_xor_sync(0xffffffffu, rsum, off);
        if (tx == 0)
            g_partial[((long long)b * CODE + o0 + orow) * NTILES + nt] = rsum;
    }
}

// ---------------------------------------------------------------------------
// Kernel 2: sequential EMA queue update. One block, 672 threads (21 warps).
// ---------------------------------------------------------------------------
__global__ __launch_bounds__(672) void queue_update_kernel(
    const float* __restrict__ queue_in, const int* __restrict__ labels_raw,
    const int* __restrict__ flag)
{
    const int t = threadIdx.x;
    for (int i = t; i < NCLASSES * MEMN * CODE; i += 672) g_queue[i] = queue_in[i];

    __shared__ float sf[CODE];
    __shared__ float s_logit[MEMN];
    __shared__ float s_fnorm;
    __syncthreads();

    if (*flag != 1) return;

    const int warp = t >> 5, lane = t & 31;

    for (int b = 0; b < BB; b++) {
        const int l = get_label(labels_raw, b);
        // feat[b, c]: deterministic fixed-order reduce of 32 tile partials, /HW
        if (t < CODE) {
            const float* p = g_partial + ((long long)b * CODE + t) * NTILES;
            float s = 0.0f;
#pragma unroll
            for (int k = 0; k < NTILES; k++) s += p[k];
            sf[t] = s * (1.0f / HW);
        }
        __syncthreads();

        if (warp < MEMN) {                 // warps 0..19: logit[m] = slot[m] . f
            const float* slot = g_queue + ((long long)l * MEMN + warp) * CODE;
            float s = 0.0f;
            for (int c = lane; c < CODE; c += 32) s += slot[c] * sf[c];
#pragma unroll
            for (int off = 16; off; off >>= 1) s += __shfl_xor_sync(0xffffffffu, s, off);
            if (lane == 0) s_logit[warp] = s;
        } else {                           // warp 20: ||f||
            float s = 0.0f;
            for (int c = lane; c < CODE; c += 32) { float v = sf[c]; s += v * v; }
#pragma unroll
            for (int off = 16; off; off >>= 1) s += __shfl_xor_sync(0xffffffffu, s, off);
            if (lane == 0) s_fnorm = sqrtf(s);
        }
        __syncthreads();

        const float fn = s_fnorm;
        for (int i = t; i < MEMN * CODE; i += 672) {
            const int m = i >> 8, c = i & 255;
            const float lg = s_logit[m];
            const float denom = fmaxf(fabsf(lg) * fn, EPSF);
            const float upd = lg * sf[c] / denom;
            float* qp = g_queue + ((long long)l * MEMN + m) * CODE + c;
            *qp = DECAYF * (*qp) + (1.0f - DECAYF) * upd;
        }
        __syncthreads();
    }
}

// ---------------------------------------------------------------------------
// Kernel 3: memory attention. Grid (HW/512, B) = 256 blocks, 128 threads.
// Each thread owns 4 consecutive n, logits in registers (f32x2 pairs),
// softmax in registers, then new_feat = q^T @ attn into out channels [0,256).
// q tile pre-duplicated as f32x2 pairs in smem (broadcast LDS.64, no packing).
// ---------------------------------------------------------------------------
__global__ __launch_bounds__(128) void attn_kernel(
    const int* __restrict__ labels_raw, float* __restrict__ out)
{
    const int b  = blockIdx.y;
    const int n0 = blockIdx.x * 512;
    const int t  = threadIdx.x;

    __shared__ ull sq2[MEMN][CODE];       // dup pairs, 40 KB
    const int l = get_label(labels_raw, b);
    const float* qsrc = g_queue + (long long)l * MEMN * CODE;
    for (int i = t; i < MEMN * CODE; i += 128) {
        float v = qsrc[i];
        (&sq2[0][0])[i] = pk2(v, v);
    }
    __syncthreads();

    const float* xb = out + ((long long)b * 2 * CODE + CODE) * HW;  // x half
    float*       ob = out + ((long long)b * 2 * CODE) * HW;         // new_feat half
    const int j = n0 + t * 4;

    ull acc2[MEMN][2];
#pragma unroll
    for (int m = 0; m < MEMN; m++) { acc2[m][0] = 0ULL; acc2[m][1] = 0ULL; }

#pragma unroll 4
    for (int c = 0; c < CODE; c++) {
        float4 xv = *(const float4*)(xb + (long long)c * HW + j);
        ull x0 = pk2(xv.x, xv.y), x1 = pk2(xv.z, xv.w);
#pragma unroll
        for (int m = 0; m < MEMN; m++) {
            ull q = sq2[m][c];
            acc2[m][0] = fma2(q, x0, acc2[m][0]);
            acc2[m][1] = fma2(q, x1, acc2[m][1]);
        }
    }

    // unpack logits -> softmax over m per lane
    float lg[MEMN][4];
#pragma unroll
    for (int m = 0; m < MEMN; m++) {
        float2 a = unpk2(acc2[m][0]), bvl = unpk2(acc2[m][1]);
        lg[m][0] = a.x; lg[m][1] = a.y; lg[m][2] = bvl.x; lg[m][3] = bvl.y;
    }
    float mx[4] = {lg[0][0], lg[0][1], lg[0][2], lg[0][3]};
#pragma unroll
    for (int m = 1; m < MEMN; m++)
#pragma unroll
        for (int k = 0; k < 4; k++) mx[k] = fmaxf(mx[k], lg[m][k]);
    float sm[4] = {0.f, 0.f, 0.f, 0.f};
#pragma unroll
    for (int m = 0; m < MEMN; m++)
#pragma unroll
        for (int k = 0; k < 4; k++) { lg[m][k] = expf(lg[m][k] - mx[k]); sm[k] += lg[m][k]; }
    float inv[4] = {1.f / sm[0], 1.f / sm[1], 1.f / sm[2], 1.f / sm[3]};
    ull at2[MEMN][2];
#pragma unroll
    for (int m = 0; m < MEMN; m++) {
        at2[m][0] = pk2(lg[m][0] * inv[0], lg[m][1] * inv[1]);
        at2[m][1] = pk2(lg[m][2] * inv[2], lg[m][3] * inv[3]);
    }

    // new_feat[c, j..j+3] = sum_m q[m][c] * attn[m]
#pragma unroll 2
    for (int c = 0; c < CODE; c++) {
        ull v0 = 0ULL, v1 = 0ULL;
#pragma unroll
        for (int m = 0; m < MEMN; m++) {
            ull q = sq2[m][c];
            v0 = fma2(q, at2[m][0], v0);
            v1 = fma2(q, at2[m][1], v1);
        }
        float2 a = unpk2(v0), bvl = unpk2(v1);
        *(float4*)(ob + (long long)c * HW + j) = make_float4(a.x, a.y, bvl.x, bvl.y);
    }
}

// ---------------------------------------------------------------------------
extern "C" void kernel_launch(void* const* d_in, const int* in_sizes, int n_in,
                              void* d_out, int out_size) {
    const float* feats  = (const float*)d_in[0];
    const float* preds  = (const float*)d_in[1];
    const int*   labels = (const int*)  d_in[2];  // width auto-detected on device
    const int*   flag   = (const int*)  d_in[3];
    const float* queue  = (const float*)d_in[4];
    const float* Wp     = (const float*)d_in[5];
    const float* bp     = (const float*)d_in[6];
    float* out = (float*)d_out;

    dim3 g1(HW / 128, CODE / 128, BB);
    gemm_proj_kernel<<<g1, 256>>>(feats, preds, Wp, bp, out);
    queue_update_kernel<<<1, 672>>>(queue, labels, flag);
    dim3 g3(HW / 512, BB);
    attn_kernel<<<g3, 128>>>(labels, out);
}

// round 6
// speedup vs baseline: 1.1888x; 1.1888x over previous
#include <cuda_runtime.h>
#include <cuda_bf16.h>
#include <cstdint>

#define BB 32
#define IN_C 512
#define HW 4096
#define CODE 256
#define NCLASSES 4
#define MEMN 20
#define DECAYF 0.9f
#define EPSF 1e-12f
#define NT2 64             // (HW/128 n-tiles) * 2 warp-n halves

typedef long long ll;

// Deterministic scratch (no atomics anywhere).
__device__ float g_partial[BB * CODE * NT2];
__device__ float g_queue[NCLASSES * MEMN * CODE];

// ---------------------------------------------------------------------------
// helpers
// ---------------------------------------------------------------------------
__device__ __forceinline__ uint32_t smem_u32(const void* p) {
    uint32_t a;
    asm("{ .reg .u64 t; cvta.to.shared.u64 t, %1; cvt.u32.u64 %0, t; }" : "=r"(a) : "l"(p));
    return a;
}
__device__ __forceinline__ void ldsm_x4(uint32_t a[4], uint32_t addr) {
    asm volatile("ldmatrix.sync.aligned.m8n8.x4.shared.b16 {%0,%1,%2,%3}, [%4];"
                 : "=r"(a[0]), "=r"(a[1]), "=r"(a[2]), "=r"(a[3]) : "r"(addr));
}
__device__ __forceinline__ void ldsm_x2t(uint32_t b[2], uint32_t addr) {
    asm volatile("ldmatrix.sync.aligned.m8n8.x2.trans.shared.b16 {%0,%1}, [%2];"
                 : "=r"(b[0]), "=r"(b[1]) : "r"(addr));
}
__device__ __forceinline__ void mma_bf16(float d[4], const uint32_t a[4], const uint32_t b[2]) {
    asm volatile("mma.sync.aligned.m16n8k16.row.col.f32.bf16.bf16.f32 "
                 "{%0,%1,%2,%3}, {%4,%5,%6,%7}, {%8,%9}, {%0,%1,%2,%3};"
                 : "+f"(d[0]), "+f"(d[1]), "+f"(d[2]), "+f"(d[3])
                 : "r"(a[0]), "r"(a[1]), "r"(a[2]), "r"(a[3]), "r"(b[0]), "r"(b[1]));
}

// bf16 hi/lo split of a float4, packed 4xbf16 -> uint2
__device__ __forceinline__ void split4(float4 v, uint2& hi, uint2& lo) {
    __nv_bfloat16 h0 = __float2bfloat16_rn(v.x), h1 = __float2bfloat16_rn(v.y);
    __nv_bfloat16 h2 = __float2bfloat16_rn(v.z), h3 = __float2bfloat16_rn(v.w);
    float r0 = v.x - __bfloat162float(h0), r1 = v.y - __bfloat162float(h1);
    float r2 = v.z - __bfloat162float(h2), r3 = v.w - __bfloat162float(h3);
    __nv_bfloat16 l0 = __float2bfloat16_rn(r0), l1 = __float2bfloat16_rn(r1);
    __nv_bfloat16 l2 = __float2bfloat16_rn(r2), l3 = __float2bfloat16_rn(r3);
    hi.x = (uint32_t)__bfloat16_as_ushort(h0) | ((uint32_t)__bfloat16_as_ushort(h1) << 16);
    hi.y = (uint32_t)__bfloat16_as_ushort(h2) | ((uint32_t)__bfloat16_as_ushort(h3) << 16);
    lo.x = (uint32_t)__bfloat16_as_ushort(l0) | ((uint32_t)__bfloat16_as_ushort(l1) << 16);
    lo.y = (uint32_t)__bfloat16_as_ushort(l2) | ((uint32_t)__bfloat16_as_ushort(l3) << 16);
}

// labels may be int32 or int64; detect on device (int64 -> odd words all zero).
__device__ __forceinline__ int get_label(const int* lab, int i) {
    bool odd_zero = true;
#pragma unroll
    for (int k = 1; k < 32; k += 2) odd_zero &= (lab[k] == 0);
    return odd_zero ? lab[2 * i] : lab[i];
}

// ===========================================================================
// Kernel 1: HMMA bf16-split GEMM. Per CTA: 128 o x 128 n, K=512 in 16 chunks
// of 32. 8 warps, warp tile 32x64. 3-split (hi*hi + hi*lo + lo*hi), fp32 acc.
// Writes x (+bias) into out channels [256,512) and masked partials (NT2=64).
// ===========================================================================
#define KC 32
#define NCHUNK 16
// A tile: [128 o][KC k] bf16, row stride 40 elems (80 B)  -> 10240 B each
// B tile: [KC k][128 n] bf16, row stride 136 elems (272 B)-> 8704 B each
#define A_STR 80
#define B_STR 272
#define A_HI 0
#define A_LO 10240
#define B_HI 20480
#define B_LO 29184
#define BUF 37888
#define PREDS (2 * BUF)
#define SMEM_GEMM (PREDS + 512 + 16)

__global__ __launch_bounds__(256) void gemm_proj_mma(
    const float* __restrict__ feats, const float* __restrict__ preds,
    const float* __restrict__ Wp, const float* __restrict__ bp,
    float* __restrict__ out)
{
    extern __shared__ char base[];
    const uint32_t sb = smem_u32(base);

    const int t = threadIdx.x, wid = t >> 5, lane = t & 31;
    const int nt = blockIdx.x, ot = blockIdx.y, b = blockIdx.z;
    const int n0 = nt * 128, o0 = ot * 128;
    const int wm = wid & 3;          // m warp tile (32 rows each)
    const int wn = wid >> 2;         // n warp tile (64 cols each)

    const float* fb = feats + (ll)b * IN_C * HW;

    // stage preds row (used in epilogue)
    if (t < 128) ((float*)(base + PREDS))[t] = preds[(ll)b * HW + n0 + t];

    float d[2][8][4];
#pragma unroll
    for (int i = 0; i < 2; i++)
#pragma unroll
        for (int j = 0; j < 8; j++)
#pragma unroll
            for (int k = 0; k < 4; k++) d[i][j][k] = 0.0f;

    // conversion thread mapping
    const int arow = t >> 1, ak = (t & 1) * 16;    // A: 128 rows x 32 k
    const int krow = t >> 3, nq = (t & 7) * 16;    // B: 32 k x 128 n

    float4 aR[4], bR[4];
    // prologue: load chunk 0
#pragma unroll
    for (int q = 0; q < 4; q++) {
        aR[q] = *(const float4*)(Wp + (ll)(o0 + arow) * IN_C + ak + q * 4);
        bR[q] = *(const float4*)(fb + (ll)krow * HW + n0 + nq + q * 4);
    }

    for (int c = 0; c < NCHUNK; c++) {
        const int buf = c & 1;
        char* bp_ = base + buf * BUF;
        // store staged regs -> smem (hi/lo split)
#pragma unroll
        for (int q = 0; q < 4; q++) {
            uint2 hi, lo;
            split4(aR[q], hi, lo);
            *(uint2*)(bp_ + A_HI + arow * A_STR + (ak + q * 4) * 2) = hi;
            *(uint2*)(bp_ + A_LO + arow * A_STR + (ak + q * 4) * 2) = lo;
            split4(bR[q], hi, lo);
            *(uint2*)(bp_ + B_HI + krow * B_STR + (nq + q * 4) * 2) = hi;
            *(uint2*)(bp_ + B_LO + krow * B_STR + (nq + q * 4) * 2) = lo;
        }
        __syncthreads();

        // prefetch next chunk while doing mma on this one
        if (c + 1 < NCHUNK) {
            const int cn = c + 1;
#pragma unroll
            for (int q = 0; q < 4; q++) {
                aR[q] = *(const float4*)(Wp + (ll)(o0 + arow) * IN_C + cn * KC + ak + q * 4);
                bR[q] = *(const float4*)(fb + (ll)(cn * KC + krow) * HW + n0 + nq + q * 4);
            }
        }

        const uint32_t bu = sb + buf * BUF;
#pragma unroll
        for (int s = 0; s < 2; s++) {
            uint32_t bh[8][2], bl[8][2];
            const int kr = s * 16 + (lane & 15);
#pragma unroll
            for (int nf = 0; nf < 8; nf++) {
                uint32_t ba = bu + B_HI + kr * B_STR + (wn * 64 + nf * 8) * 2;
                ldsm_x2t(bh[nf], ba);
                ldsm_x2t(bl[nf], ba + (B_LO - B_HI));
            }
#pragma unroll
            for (int mf = 0; mf < 2; mf++) {
                const int ar = wm * 32 + mf * 16 + (lane & 15);
                const uint32_t acol = (s * 16 + ((lane >> 4) << 3)) * 2;
                uint32_t aa = bu + A_HI + ar * A_STR + acol;
                uint32_t ah[4], al[4];
                ldsm_x4(ah, aa);
                ldsm_x4(al, aa + (A_LO - A_HI));
                // 3 split terms, nf-inner to break accumulator RAW chains
#pragma unroll
                for (int nf = 0; nf < 8; nf++) mma_bf16(d[mf][nf], ah, bh[nf]);
#pragma unroll
                for (int nf = 0; nf < 8; nf++) mma_bf16(d[mf][nf], ah, bl[nf]);
#pragma unroll
                for (int nf = 0; nf < 8; nf++) mma_bf16(d[mf][nf], al, bh[nf]);
            }
        }
        __syncthreads();
    }

    // ---- epilogue ----
    const float* ps = (const float*)(base + PREDS);
    const int r = lane >> 2, cq = lane & 3;
#pragma unroll
    for (int mf = 0; mf < 2; mf++) {
        const int oa = o0 + wm * 32 + mf * 16 + r;
        const int oc = oa + 8;
        const float biasa = bp[oa], biasb = bp[oc];
        float* xa = out + ((ll)b * 2 * CODE + CODE + oa) * HW + n0;
        float* xc = out + ((ll)b * 2 * CODE + CODE + oc) * HW + n0;
        float ra = 0.0f, rb = 0.0f;
#pragma unroll
        for (int nf = 0; nf < 8; nf++) {
            const int nl = wn * 64 + nf * 8 + cq * 2;
            const float p0 = ps[nl], p1 = ps[nl + 1];
            float v0 = d[mf][nf][0] + biasa, v1 = d[mf][nf][1] + biasa;
            float v2 = d[mf][nf][2] + biasb, v3 = d[mf][nf][3] + biasb;
            ra += v0 * p0 + v1 * p1;
            rb += v2 * p0 + v3 * p1;
            *(float2*)(xa + nl) = make_float2(v0, v1);
            *(float2*)(xc + nl) = make_float2(v2, v3);
        }
        ra += __shfl_xor_sync(0xffffffffu, ra, 1);
        ra += __shfl_xor_sync(0xffffffffu, ra, 2);
        rb += __shfl_xor_sync(0xffffffffu, rb, 1);
        rb += __shfl_xor_sync(0xffffffffu, rb, 2);
        if (cq == 0) {
            g_partial[((ll)b * CODE + oa) * NT2 + nt * 2 + wn] = ra;
            g_partial[((ll)b * CODE + oc) * NT2 + nt * 2 + wn] = rb;
        }
    }
}

// ===========================================================================
// Kernel 2: sequential EMA queue update. One block, 672 threads (21 warps).
// ===========================================================================
__global__ __launch_bounds__(672) void queue_update_kernel(
    const float* __restrict__ queue_in, const int* __restrict__ labels_raw,
    const int* __restrict__ flag)
{
    const int t = threadIdx.x;
    for (int i = t; i < NCLASSES * MEMN * CODE; i += 672) g_queue[i] = queue_in[i];

    __shared__ float sf[CODE];
    __shared__ float s_logit[MEMN];
    __shared__ float s_fnorm;
    __syncthreads();

    if (*flag != 1) return;

    const int warp = t >> 5, lane = t & 31;

    for (int b = 0; b < BB; b++) {
        const int l = get_label(labels_raw, b);
        if (t < CODE) {
            const float* p = g_partial + ((ll)b * CODE + t) * NT2;
            float s = 0.0f;
#pragma unroll
            for (int k = 0; k < NT2; k++) s += p[k];
            sf[t] = s * (1.0f / HW);
        }
        __syncthreads();

        if (warp < MEMN) {
            const float* slot = g_queue + ((ll)l * MEMN + warp) * CODE;
            float s = 0.0f;
            for (int c = lane; c < CODE; c += 32) s += slot[c] * sf[c];
#pragma unroll
            for (int off = 16; off; off >>= 1) s += __shfl_xor_sync(0xffffffffu, s, off);
            if (lane == 0) s_logit[warp] = s;
        } else {
            float s = 0.0f;
            for (int c = lane; c < CODE; c += 32) { float v = sf[c]; s += v * v; }
#pragma unroll
            for (int off = 16; off; off >>= 1) s += __shfl_xor_sync(0xffffffffu, s, off);
            if (lane == 0) s_fnorm = sqrtf(s);
        }
        __syncthreads();

        const float fn = s_fnorm;
        for (int i = t; i < MEMN * CODE; i += 672) {
            const int m = i >> 8, c = i & 255;
            const float lg = s_logit[m];
            const float denom = fmaxf(fabsf(lg) * fn, EPSF);
            const float upd = lg * sf[c] / denom;
            float* qp = g_queue + ((ll)l * MEMN + m) * CODE + c;
            *qp = DECAYF * (*qp) + (1.0f - DECAYF) * upd;
        }
        __syncthreads();
    }
}

// ===========================================================================
// Kernel 3: memory attention. Grid (HW/512, B) = 256 blocks, 256 threads.
// 2 n per thread (float2 accs), LDS.128 over c-quads.
// ===========================================================================
__global__ __launch_bounds__(256) void attn_kernel(
    const int* __restrict__ labels_raw, float* __restrict__ out)
{
    const int b = blockIdx.y, n0 = blockIdx.x * 512, t = threadIdx.x;

    __shared__ float sq[MEMN][CODE];
    const int l = get_label(labels_raw, b);
    const float* qsrc = g_queue + (ll)l * MEMN * CODE;
    for (int i = t * 4; i < MEMN * CODE; i += 1024)
        *(float4*)(&sq[0][0] + i) = *(const float4*)(qsrc + i);
    __syncthreads();

    const float* xb = out + ((ll)b * 2 * CODE + CODE) * HW;
    float* ob = out + ((ll)b * 2 * CODE) * HW;
    const int j = n0 + t * 2;

    float a0[MEMN], a1[MEMN];
#pragma unroll
    for (int m = 0; m < MEMN; m++) { a0[m] = 0.f; a1[m] = 0.f; }

    for (int cqd = 0; cqd < 64; cqd++) {
        const float* xp = xb + (ll)cqd * 4 * HW + j;
        float2 x0 = *(const float2*)(xp);
        float2 x1 = *(const float2*)(xp + HW);
        float2 x2 = *(const float2*)(xp + 2 * HW);
        float2 x3 = *(const float2*)(xp + 3 * HW);
#pragma unroll
        for (int m = 0; m < MEMN; m++) {
            float4 qv = *(const float4*)&sq[m][cqd * 4];
            a0[m] += qv.x * x0.x + qv.y * x1.x + qv.z * x2.x + qv.w * x3.x;
            a1[m] += qv.x * x0.y + qv.y * x1.y + qv.z * x2.y + qv.w * x3.y;
        }
    }

    float m0 = a0[0], m1 = a1[0];
#pragma unroll
    for (int m = 1; m < MEMN; m++) { m0 = fmaxf(m0, a0[m]); m1 = fmaxf(m1, a1[m]); }
    float s0 = 0.f, s1 = 0.f;
#pragma unroll
    for (int m = 0; m < MEMN; m++) {
        a0[m] = expf(a0[m] - m0); s0 += a0[m];
        a1[m] = expf(a1[m] - m1); s1 += a1[m];
    }
    const float i0 = 1.f / s0, i1 = 1.f / s1;
#pragma unroll
    for (int m = 0; m < MEMN; m++) { a0[m] *= i0; a1[m] *= i1; }

    for (int cqd = 0; cqd < 64; cqd++) {
        float o0x = 0.f, o0y = 0.f, o1x = 0.f, o1y = 0.f;
        float o2x = 0.f, o2y = 0.f, o3x = 0.f, o3y = 0.f;
#pragma unroll
        for (int m = 0; m < MEMN; m++) {
            float4 qv = *(const float4*)&sq[m][cqd * 4];
            o0x += qv.x * a0[m]; o0y += qv.x * a1[m];
            o1x += qv.y * a0[m]; o1y += qv.y * a1[m];
            o2x += qv.z * a0[m]; o2y += qv.z * a1[m];
            o3x += qv.w * a0[m]; o3y += qv.w * a1[m];
        }
        float* op = ob + (ll)cqd * 4 * HW + j;
        *(float2*)(op)          = make_float2(o0x, o0y);
        *(float2*)(op + HW)     = make_float2(o1x, o1y);
        *(float2*)(op + 2 * HW) = make_float2(o2x, o2y);
        *(float2*)(op + 3 * HW) = make_float2(o3x, o3y);
    }
}

// ---------------------------------------------------------------------------
extern "C" void kernel_launch(void* const* d_in, const int* in_sizes, int n_in,
                              void* d_out, int out_size) {
    const float* feats  = (const float*)d_in[0];
    const float* preds  = (const float*)d_in[1];
    const int*   labels = (const int*)  d_in[2];
    const int*   flag   = (const int*)  d_in[3];
    const float* queue  = (const float*)d_in[4];
    const float* Wp     = (const float*)d_in[5];
    const float* bp     = (const float*)d_in[6];
    float* out = (float*)d_out;

    cudaFuncSetAttribute(gemm_proj_mma,
                         cudaFuncAttributeMaxDynamicSharedMemorySize, SMEM_GEMM);

    dim3 g1(HW / 128, CODE / 128, BB);
    gemm_proj_mma<<<g1, 256, SMEM_GEMM>>>(feats, preds, Wp, bp, out);
    queue_update_kernel<<<1, 672>>>(queue, labels, flag);
    dim3 g3(HW / 512, BB);
    attn_kernel<<<g3, 256>>>(labels, out);
}

// round 7
// speedup vs baseline: 1.9207x; 1.6156x over previous
#include <cuda_runtime.h>
#include <cuda_bf16.h>
#include <cstdint>

#define BB 32
#define IN_C 512
#define HW 4096
#define CODE 256
#define NCLASSES 4
#define MEMN 20
#define DECAYF 0.9f
#define EPSF 1e-12f
#define NT2 64             // (HW/128 n-tiles) * 2 warp-n halves

typedef long long ll;

// Deterministic scratch (no atomics anywhere).
__device__ float g_partial[BB * CODE * NT2];
__device__ float g_feat[BB * CODE];
__device__ float g_queue[NCLASSES * MEMN * CODE];

// Pre-converted bf16 hi/lo operands (elementwise split of fp32).
__device__ __nv_bfloat16 g_wp_hi[CODE * IN_C];
__device__ __nv_bfloat16 g_wp_lo[CODE * IN_C];
__device__ __nv_bfloat16 g_f_hi[(ll)BB * IN_C * HW];
__device__ __nv_bfloat16 g_f_lo[(ll)BB * IN_C * HW];

// ---------------------------------------------------------------------------
// helpers
// ---------------------------------------------------------------------------
__device__ __forceinline__ uint32_t smem_u32(const void* p) {
    uint32_t a;
    asm("{ .reg .u64 t; cvta.to.shared.u64 t, %1; cvt.u32.u64 %0, t; }" : "=r"(a) : "l"(p));
    return a;
}
__device__ __forceinline__ void ldsm_x4(uint32_t a[4], uint32_t addr) {
    asm volatile("ldmatrix.sync.aligned.m8n8.x4.shared.b16 {%0,%1,%2,%3}, [%4];"
                 : "=r"(a[0]), "=r"(a[1]), "=r"(a[2]), "=r"(a[3]) : "r"(addr));
}
__device__ __forceinline__ void ldsm_x2t(uint32_t b[2], uint32_t addr) {
    asm volatile("ldmatrix.sync.aligned.m8n8.x2.trans.shared.b16 {%0,%1}, [%2];"
                 : "=r"(b[0]), "=r"(b[1]) : "r"(addr));
}
__device__ __forceinline__ void mma_bf16(float d[4], const uint32_t a[4], const uint32_t b[2]) {
    asm volatile("mma.sync.aligned.m16n8k16.row.col.f32.bf16.bf16.f32 "
                 "{%0,%1,%2,%3}, {%4,%5,%6,%7}, {%8,%9}, {%0,%1,%2,%3};"
                 : "+f"(d[0]), "+f"(d[1]), "+f"(d[2]), "+f"(d[3])
                 : "r"(a[0]), "r"(a[1]), "r"(a[2]), "r"(a[3]), "r"(b[0]), "r"(b[1]));
}
__device__ __forceinline__ void cpasync16(uint32_t dst, const void* src) {
    asm volatile("cp.async.cg.shared.global [%0], [%1], 16;" :: "r"(dst), "l"(src));
}
#define CP_COMMIT() asm volatile("cp.async.commit_group;" ::: "memory")
#define CP_WAIT0()  asm volatile("cp.async.wait_group 0;" ::: "memory")
#define CP_WAIT1()  asm volatile("cp.async.wait_group 1;" ::: "memory")

// bf16 hi/lo split of a float4, packed 4xbf16 -> uint2
__device__ __forceinline__ void split4(float4 v, uint2& hi, uint2& lo) {
    __nv_bfloat16 h0 = __float2bfloat16_rn(v.x), h1 = __float2bfloat16_rn(v.y);
    __nv_bfloat16 h2 = __float2bfloat16_rn(v.z), h3 = __float2bfloat16_rn(v.w);
    float r0 = v.x - __bfloat162float(h0), r1 = v.y - __bfloat162float(h1);
    float r2 = v.z - __bfloat162float(h2), r3 = v.w - __bfloat162float(h3);
    __nv_bfloat16 l0 = __float2bfloat16_rn(r0), l1 = __float2bfloat16_rn(r1);
    __nv_bfloat16 l2 = __float2bfloat16_rn(r2), l3 = __float2bfloat16_rn(r3);
    hi.x = (uint32_t)__bfloat16_as_ushort(h0) | ((uint32_t)__bfloat16_as_ushort(h1) << 16);
    hi.y = (uint32_t)__bfloat16_as_ushort(h2) | ((uint32_t)__bfloat16_as_ushort(h3) << 16);
    lo.x = (uint32_t)__bfloat16_as_ushort(l0) | ((uint32_t)__bfloat16_as_ushort(l1) << 16);
    lo.y = (uint32_t)__bfloat16_as_ushort(l2) | ((uint32_t)__bfloat16_as_ushort(l3) << 16);
}

// labels may be int32 or int64; detect on device (int64 -> odd words all zero).
__device__ __forceinline__ int get_label(const int* lab, int i) {
    bool odd_zero = true;
#pragma unroll
    for (int k = 1; k < 32; k += 2) odd_zero &= (lab[k] == 0);
    return odd_zero ? lab[2 * i] : lab[i];
}

// ===========================================================================
// Kernel 0a/0b: elementwise fp32 -> bf16 hi/lo pre-conversion.
// ===========================================================================
__global__ __launch_bounds__(256) void convert_wp(const float* __restrict__ Wp) {
    const int i = (blockIdx.x * 256 + threadIdx.x) * 4;
    float4 v = *(const float4*)(Wp + i);
    uint2 hi, lo; split4(v, hi, lo);
    *(uint2*)(g_wp_hi + i) = hi;
    *(uint2*)(g_wp_lo + i) = lo;
}
__global__ __launch_bounds__(1024) void convert_feats(const float* __restrict__ feats) {
    const ll i = ((ll)blockIdx.x * 1024 + threadIdx.x) * 4;
    float4 v = *(const float4*)(feats + i);
    uint2 hi, lo; split4(v, hi, lo);
    *(uint2*)(g_f_hi + i) = hi;
    *(uint2*)(g_f_lo + i) = lo;
}

// ===========================================================================
// Kernel 1: HMMA bf16-split GEMM with cp.async double-buffer pipeline.
// Per CTA: 128 o x 128 n, K=512 in 16 chunks of 32. 8 warps, warp tile 32x64.
// 3-split (hi*hi + hi*lo + lo*hi), fp32 acc. 2 CTAs/SM.
// Writes x (+bias) into out channels [256,512) and masked partials (NT2=64).
// ===========================================================================
#define KC 32
#define NCHUNK 16
// A tile: [128 o][KC k] bf16, row stride 80 B  -> 10240 B each
// B tile: [KC k][128 n] bf16, row stride 272 B -> 8704 B each
#define A_STR 80
#define B_STR 272
#define A_HI 0
#define A_LO 10240
#define B_HI 20480
#define B_LO 29184
#define BUF 37888
#define PREDS (2 * BUF)
#define SMEM_GEMM (PREDS + 512 + 16)

__global__ __launch_bounds__(256, 2) void gemm_proj_mma(
    const float* __restrict__ preds, const float* __restrict__ bp,
    float* __restrict__ out)
{
    extern __shared__ char base[];
    const uint32_t sb = smem_u32(base);

    const int t = threadIdx.x, wid = t >> 5, lane = t & 31;
    const int nt = blockIdx.x, ot = blockIdx.y, b = blockIdx.z;
    const int n0 = nt * 128, o0 = ot * 128;
    const int wm = wid & 3;          // m warp tile (32 rows each)
    const int wn = wid >> 2;         // n warp tile (64 cols each)

    // cp.async thread mapping
    const int ar = t >> 1, as0 = (t & 1) * 2;      // A: 128 rows x 4 segs
    const int bk = t >> 3, bs0 = (t & 7) * 2;      // B: 32 rows x 16 segs
    const __nv_bfloat16* wha = g_wp_hi + (ll)(o0 + ar) * IN_C + as0 * 8;
    const __nv_bfloat16* wla = g_wp_lo + (ll)(o0 + ar) * IN_C + as0 * 8;
    const __nv_bfloat16* fha = g_f_hi + ((ll)b * IN_C + bk) * HW + n0 + bs0 * 8;
    const __nv_bfloat16* fla = g_f_lo + ((ll)b * IN_C + bk) * HW + n0 + bs0 * 8;
    const uint32_t adst = sb + A_HI + ar * A_STR + as0 * 16;
    const uint32_t bdst = sb + B_HI + bk * B_STR + bs0 * 16;

    // stage preds row (used in epilogue)
    if (t < 128) ((float*)(base + PREDS))[t] = preds[(ll)b * HW + n0 + t];

    float d[2][8][4];
#pragma unroll
    for (int i = 0; i < 2; i++)
#pragma unroll
        for (int j = 0; j < 8; j++)
#pragma unroll
            for (int k = 0; k < 4; k++) d[i][j][k] = 0.0f;

    // prologue: issue chunk 0 into buffer 0
    {
        cpasync16(adst,       wha);
        cpasync16(adst + 16,  wha + 8);
        cpasync16(adst + (A_LO - A_HI),      wla);
        cpasync16(adst + (A_LO - A_HI) + 16, wla + 8);
        cpasync16(bdst,       fha);
        cpasync16(bdst + 16,  fha + 8);
        cpasync16(bdst + (B_LO - B_HI),      fla);
        cpasync16(bdst + (B_LO - B_HI) + 16, fla + 8);
        CP_COMMIT();
    }

    for (int c = 0; c < NCHUNK; c++) {
        if (c + 1 < NCHUNK) {
            const uint32_t db = ((c + 1) & 1) * BUF;
            const ll ko = (ll)(c + 1) * KC;
            cpasync16(adst + db,       wha + ko);
            cpasync16(adst + db + 16,  wha + ko + 8);
            cpasync16(adst + db + (A_LO - A_HI),      wla + ko);
            cpasync16(adst + db + (A_LO - A_HI) + 16, wla + ko + 8);
            cpasync16(bdst + db,       fha + ko * HW);
            cpasync16(bdst + db + 16,  fha + ko * HW + 8);
            cpasync16(bdst + db + (B_LO - B_HI),      fla + ko * HW);
            cpasync16(bdst + db + (B_LO - B_HI) + 16, fla + ko * HW + 8);
            CP_COMMIT();
            CP_WAIT1();
        } else {
            CP_WAIT0();
        }
        __syncthreads();

        const uint32_t bu = sb + (c & 1) * BUF;
#pragma unroll
        for (int s = 0; s < 2; s++) {
            uint32_t bh[8][2], bl[8][2];
            const int kr = s * 16 + (lane & 15);
#pragma unroll
            for (int nf = 0; nf < 8; nf++) {
                uint32_t ba = bu + B_HI + kr * B_STR + (wn * 64 + nf * 8) * 2;
                ldsm_x2t(bh[nf], ba);
                ldsm_x2t(bl[nf], ba + (B_LO - B_HI));
            }
#pragma unroll
            for (int mf = 0; mf < 2; mf++) {
                const int arr = wm * 32 + mf * 16 + (lane & 15);
                const uint32_t acol = (s * 16 + ((lane >> 4) << 3)) * 2;
                uint32_t aa = bu + A_HI + arr * A_STR + acol;
                uint32_t ah[4], al[4];
                ldsm_x4(ah, aa);
                ldsm_x4(al, aa + (A_LO - A_HI));
#pragma unroll
                for (int nf = 0; nf < 8; nf++) mma_bf16(d[mf][nf], ah, bh[nf]);
#pragma unroll
                for (int nf = 0; nf < 8; nf++) mma_bf16(d[mf][nf], ah, bl[nf]);
#pragma unroll
                for (int nf = 0; nf < 8; nf++) mma_bf16(d[mf][nf], al, bh[nf]);
            }
        }
        __syncthreads();
    }

    // ---- epilogue ----
    const float* ps = (const float*)(base + PREDS);
    const int r = lane >> 2, cq = lane & 3;
#pragma unroll
    for (int mf = 0; mf < 2; mf++) {
        const int oa = o0 + wm * 32 + mf * 16 + r;
        const int oc = oa + 8;
        const float biasa = bp[oa], biasb = bp[oc];
        float* xa = out + ((ll)b * 2 * CODE + CODE + oa) * HW + n0;
        float* xc = out + ((ll)b * 2 * CODE + CODE + oc) * HW + n0;
        float ra = 0.0f, rb = 0.0f;
#pragma unroll
        for (int nf = 0; nf < 8; nf++) {
            const int nl = wn * 64 + nf * 8 + cq * 2;
            const float p0 = ps[nl], p1 = ps[nl + 1];
            float v0 = d[mf][nf][0] + biasa, v1 = d[mf][nf][1] + biasa;
            float v2 = d[mf][nf][2] + biasb, v3 = d[mf][nf][3] + biasb;
            ra += v0 * p0 + v1 * p1;
            rb += v2 * p0 + v3 * p1;
            *(float2*)(xa + nl) = make_float2(v0, v1);
            *(float2*)(xc + nl) = make_float2(v2, v3);
        }
        ra += __shfl_xor_sync(0xffffffffu, ra, 1);
        ra += __shfl_xor_sync(0xffffffffu, ra, 2);
        rb += __shfl_xor_sync(0xffffffffu, rb, 1);
        rb += __shfl_xor_sync(0xffffffffu, rb, 2);
        if (cq == 0) {
            g_partial[((ll)b * CODE + oa) * NT2 + nt * 2 + wn] = ra;
            g_partial[((ll)b * CODE + oc) * NT2 + nt * 2 + wn] = rb;
        }
    }
}

// ===========================================================================
// Kernel 2a: parallel feat reduction. Grid 32 (one per b), 256 threads.
// ===========================================================================
__global__ __launch_bounds__(256) void feat_reduce_kernel() {
    const int b = blockIdx.x, t = threadIdx.x;
    const float* p = g_partial + ((ll)b * CODE + t) * NT2;
    float s = 0.0f;
#pragma unroll
    for (int k = 0; k < NT2; k++) s += p[k];
    g_feat[b * CODE + t] = s * (1.0f / HW);
}

// ===========================================================================
// Kernel 2b: sequential EMA scan, fully in shared memory.
// One block, 672 threads (21 warps). smem: queue (80KB) + feats (32KB).
// ===========================================================================
#define SMEM_SCAN ((NCLASSES * MEMN * CODE + BB * CODE + 32) * 4)

__global__ __launch_bounds__(672) void queue_scan_kernel(
    const float* __restrict__ queue_in, const int* __restrict__ labels_raw,
    const int* __restrict__ flag)
{
    extern __shared__ float sm[];
    float* s_q = sm;                                   // 20480
    float* s_feat = sm + NCLASSES * MEMN * CODE;       // 8192
    float* s_logit = s_feat + BB * CODE;               // 20
    float* s_fnorm = s_logit + MEMN;                   // 1

    const int t = threadIdx.x;
    for (int i = t; i < NCLASSES * MEMN * CODE; i += 672) s_q[i] = queue_in[i];
    for (int i = t; i < BB * CODE; i += 672) s_feat[i] = g_feat[i];
    __syncthreads();

    if (*flag == 1) {
        const int warp = t >> 5, lane = t & 31;
        for (int b = 0; b < BB; b++) {
            const int l = get_label(labels_raw, b);
            const float* f = s_feat + b * CODE;

            if (warp < MEMN) {
                const float* slot = s_q + (l * MEMN + warp) * CODE;
                float s = 0.0f;
#pragma unroll
                for (int c = lane; c < CODE; c += 32) s += slot[c] * f[c];
#pragma unroll
                for (int off = 16; off; off >>= 1) s += __shfl_xor_sync(0xffffffffu, s, off);
                if (lane == 0) s_logit[warp] = s;
            } else {
                float s = 0.0f;
#pragma unroll
                for (int c = lane; c < CODE; c += 32) { float v = f[c]; s += v * v; }
#pragma unroll
                for (int off = 16; off; off >>= 1) s += __shfl_xor_sync(0xffffffffu, s, off);
                if (lane == 0) *s_fnorm = sqrtf(s);
            }
            __syncthreads();

            const float fn = *s_fnorm;
            for (int i = t; i < MEMN * CODE; i += 672) {
                const int m = i >> 8, c = i & 255;
                const float lg = s_logit[m];
                const float denom = fmaxf(fabsf(lg) * fn, EPSF);
                const float upd = lg * f[c] / denom;
                float* qp = s_q + (l * MEMN + m) * CODE + c;
                *qp = DECAYF * (*qp) + (1.0f - DECAYF) * upd;
            }
            __syncthreads();
        }
    }

    for (int i = t; i < NCLASSES * MEMN * CODE; i += 672) g_queue[i] = s_q[i];
}

// ===========================================================================
// Kernel 3: memory attention. Grid (HW/512, B) = 256 blocks, 256 threads.
// 2 n per thread (float2 accs), LDS.128 over c-quads.
// ===========================================================================
__global__ __launch_bounds__(256) void attn_kernel(
    const int* __restrict__ labels_raw, float* __restrict__ out)
{
    const int b = blockIdx.y, n0 = blockIdx.x * 512, t = threadIdx.x;

    __shared__ float sq[MEMN][CODE];
    const int l = get_label(labels_raw, b);
    const float* qsrc = g_queue + (ll)l * MEMN * CODE;
    for (int i = t * 4; i < MEMN * CODE; i += 1024)
        *(float4*)(&sq[0][0] + i) = *(const float4*)(qsrc + i);
    __syncthreads();

    const float* xb = out + ((ll)b * 2 * CODE + CODE) * HW;
    float* ob = out + ((ll)b * 2 * CODE) * HW;
    const int j = n0 + t * 2;

    float a0[MEMN], a1[MEMN];
#pragma unroll
    for (int m = 0; m < MEMN; m++) { a0[m] = 0.f; a1[m] = 0.f; }

    for (int cqd = 0; cqd < 64; cqd++) {
        const float* xp = xb + (ll)cqd * 4 * HW + j;
        float2 x0 = *(const float2*)(xp);
        float2 x1 = *(const float2*)(xp + HW);
        float2 x2 = *(const float2*)(xp + 2 * HW);
        float2 x3 = *(const float2*)(xp + 3 * HW);
#pragma unroll
        for (int m = 0; m < MEMN; m++) {
            float4 qv = *(const float4*)&sq[m][cqd * 4];
            a0[m] += qv.x * x0.x + qv.y * x1.x + qv.z * x2.x + qv.w * x3.x;
            a1[m] += qv.x * x0.y + qv.y * x1.y + qv.z * x2.y + qv.w * x3.y;
        }
    }

    float m0 = a0[0], m1 = a1[0];
#pragma unroll
    for (int m = 1; m < MEMN; m++) { m0 = fmaxf(m0, a0[m]); m1 = fmaxf(m1, a1[m]); }
    float s0 = 0.f, s1 = 0.f;
#pragma unroll
    for (int m = 0; m < MEMN; m++) {
        a0[m] = expf(a0[m] - m0); s0 += a0[m];
        a1[m] = expf(a1[m] - m1); s1 += a1[m];
    }
    const float i0 = 1.f / s0, i1 = 1.f / s1;
#pragma unroll
    for (int m = 0; m < MEMN; m++) { a0[m] *= i0; a1[m] *= i1; }

    for (int cqd = 0; cqd < 64; cqd++) {
        float o0x = 0.f, o0y = 0.f, o1x = 0.f, o1y = 0.f;
        float o2x = 0.f, o2y = 0.f, o3x = 0.f, o3y = 0.f;
#pragma unroll
        for (int m = 0; m < MEMN; m++) {
            float4 qv = *(const float4*)&sq[m][cqd * 4];
            o0x += qv.x * a0[m]; o0y += qv.x * a1[m];
            o1x += qv.y * a0[m]; o1y += qv.y * a1[m];
            o2x += qv.z * a0[m]; o2y += qv.z * a1[m];
            o3x += qv.w * a0[m]; o3y += qv.w * a1[m];
        }
        float* op = ob + (ll)cqd * 4 * HW + j;
        *(float2*)(op)          = make_float2(o0x, o0y);
        *(float2*)(op + HW)     = make_float2(o1x, o1y);
        *(float2*)(op + 2 * HW) = make_float2(o2x, o2y);
        *(float2*)(op + 3 * HW) = make_float2(o3x, o3y);
    }
}

// ---------------------------------------------------------------------------
extern "C" void kernel_launch(void* const* d_in, const int* in_sizes, int n_in,
                              void* d_out, int out_size) {
    const float* feats  = (const float*)d_in[0];
    const float* preds  = (const float*)d_in[1];
    const int*   labels = (const int*)  d_in[2];
    const int*   flag   = (const int*)  d_in[3];
    const float* queue  = (const float*)d_in[4];
    const float* Wp     = (const float*)d_in[5];
    const float* bp     = (const float*)d_in[6];
    float* out = (float*)d_out;

    cudaFuncSetAttribute(gemm_proj_mma,
                         cudaFuncAttributeMaxDynamicSharedMemorySize, SMEM_GEMM);
    cudaFuncSetAttribute(queue_scan_kernel,
                         cudaFuncAttributeMaxDynamicSharedMemorySize, SMEM_SCAN);

    convert_wp<<<CODE * IN_C / 1024, 256>>>(Wp);
    convert_feats<<<(int)((ll)BB * IN_C * HW / 4096), 1024>>>(feats);

    dim3 g1(HW / 128, CODE / 128, BB);
    gemm_proj_mma<<<g1, 256, SMEM_GEMM>>>(preds, bp, out);

    feat_reduce_kernel<<<BB, 256>>>();
    queue_scan_kernel<<<1, 672, SMEM_SCAN>>>(queue, labels, flag);

    dim3 g3(HW / 512, BB);
    attn_kernel<<<g3, 256>>>(labels, out);
}

// round 8
// speedup vs baseline: 1.9818x; 1.0319x over previous
#include <cuda_runtime.h>
#include <cuda_bf16.h>
#include <cstdint>

#define BB 32
#define IN_C 512
#define HW 4096
#define CODE 256
#define NCLASSES 4
#define MEMN 20
#define DECAYF 0.9f
#define EPSF 1e-12f
#define NTP 128            // partials per (b,o): 32 n-tiles x 4 wn quarters

typedef long long ll;

// Deterministic scratch (no atomics anywhere).
__device__ float g_partial[BB * CODE * NTP];
__device__ float g_feat[BB * CODE];
__device__ float g_queue[NCLASSES * MEMN * CODE];

// Pre-converted bf16 hi/lo of Wp only (tiny).
__device__ __nv_bfloat16 g_wp_hi[CODE * IN_C];
__device__ __nv_bfloat16 g_wp_lo[CODE * IN_C];

// ---------------------------------------------------------------------------
// helpers
// ---------------------------------------------------------------------------
__device__ __forceinline__ uint32_t smem_u32(const void* p) {
    uint32_t a;
    asm("{ .reg .u64 t; cvta.to.shared.u64 t, %1; cvt.u32.u64 %0, t; }" : "=r"(a) : "l"(p));
    return a;
}
__device__ __forceinline__ void ldsm_x4(uint32_t a[4], uint32_t addr) {
    asm volatile("ldmatrix.sync.aligned.m8n8.x4.shared.b16 {%0,%1,%2,%3}, [%4];"
                 : "=r"(a[0]), "=r"(a[1]), "=r"(a[2]), "=r"(a[3]) : "r"(addr));
}
__device__ __forceinline__ void ldsm_x2t(uint32_t b[2], uint32_t addr) {
    asm volatile("ldmatrix.sync.aligned.m8n8.x2.trans.shared.b16 {%0,%1}, [%2];"
                 : "=r"(b[0]), "=r"(b[1]) : "r"(addr));
}
__device__ __forceinline__ void mma_bf16(float d[4], const uint32_t a[4], const uint32_t b[2]) {
    asm volatile("mma.sync.aligned.m16n8k16.row.col.f32.bf16.bf16.f32 "
                 "{%0,%1,%2,%3}, {%4,%5,%6,%7}, {%8,%9}, {%0,%1,%2,%3};"
                 : "+f"(d[0]), "+f"(d[1]), "+f"(d[2]), "+f"(d[3])
                 : "r"(a[0]), "r"(a[1]), "r"(a[2]), "r"(a[3]), "r"(b[0]), "r"(b[1]));
}
__device__ __forceinline__ void cpasync16(uint32_t dst, const void* src) {
    asm volatile("cp.async.cg.shared.global [%0], [%1], 16;" :: "r"(dst), "l"(src));
}
#define CP_COMMIT() asm volatile("cp.async.commit_group;" ::: "memory")
#define CP_WAIT0()  asm volatile("cp.async.wait_group 0;" ::: "memory")

// bf16 hi/lo split of a float4, packed 4xbf16 -> uint2
__device__ __forceinline__ void split4(float4 v, uint2& hi, uint2& lo) {
    __nv_bfloat16 h0 = __float2bfloat16_rn(v.x), h1 = __float2bfloat16_rn(v.y);
    __nv_bfloat16 h2 = __float2bfloat16_rn(v.z), h3 = __float2bfloat16_rn(v.w);
    float r0 = v.x - __bfloat162float(h0), r1 = v.y - __bfloat162float(h1);
    float r2 = v.z - __bfloat162float(h2), r3 = v.w - __bfloat162float(h3);
    __nv_bfloat16 l0 = __float2bfloat16_rn(r0), l1 = __float2bfloat16_rn(r1);
    __nv_bfloat16 l2 = __float2bfloat16_rn(r2), l3 = __float2bfloat16_rn(r3);
    hi.x = (uint32_t)__bfloat16_as_ushort(h0) | ((uint32_t)__bfloat16_as_ushort(h1) << 16);
    hi.y = (uint32_t)__bfloat16_as_ushort(h2) | ((uint32_t)__bfloat16_as_ushort(h3) << 16);
    lo.x = (uint32_t)__bfloat16_as_ushort(l0) | ((uint32_t)__bfloat16_as_ushort(l1) << 16);
    lo.y = (uint32_t)__bfloat16_as_ushort(l2) | ((uint32_t)__bfloat16_as_ushort(l3) << 16);
}

// labels may be int32 or int64; detect on device (int64 -> odd words all zero).
__device__ __forceinline__ int get_label(const int* lab, int i) {
    bool odd_zero = true;
#pragma unroll
    for (int k = 1; k < 32; k += 2) odd_zero &= (lab[k] == 0);
    return odd_zero ? lab[2 * i] : lab[i];
}

// ===========================================================================
// Kernel 0: Wp fp32 -> bf16 hi/lo (131072 elems, trivial).
// ===========================================================================
__global__ __launch_bounds__(256) void convert_wp(const float* __restrict__ Wp) {
    const int i = (blockIdx.x * 256 + threadIdx.x) * 4;
    float4 v = *(const float4*)(Wp + i);
    uint2 hi, lo; split4(v, hi, lo);
    *(uint2*)(g_wp_hi + i) = hi;
    *(uint2*)(g_wp_lo + i) = lo;
}

// ===========================================================================
// Kernel 1: HMMA bf16-split GEMM, fused B conversion.
// Per CTA: 128 o x 128 n, K=512 in 16 chunks of 32. 512 threads, 16 warps,
// warp tile 32x32 (4m x 4n). 3-split (AhBh + AhBl + AlBh), fp32 acc.
// A (Wp bf16 pre-split) via cp.async; B (feats fp32) LDG->regs->split->STS.
// Writes x (+bias) into out channels [256,512) and masked partials (NTP).
// ===========================================================================
#define KC 32
#define NCHUNK 16
// A tile: [128 o][KC k] bf16, row stride 80 B  -> 10240 B per region
// B tile: [KC k][128 n] bf16, row stride 272 B -> 8704 B per region
#define A_STR 80
#define B_STR 272
#define A_HI 0
#define A_LO 10240
#define B_HI 20480
#define B_LO 29184
#define BUF 37888
#define PREDS (2 * BUF)
#define SMEM_GEMM (PREDS + 512 + 16)

__global__ __launch_bounds__(512, 1) void gemm_proj_mma(
    const float* __restrict__ feats, const float* __restrict__ preds,
    const float* __restrict__ bias_p, float* __restrict__ out)
{
    extern __shared__ char base[];
    const uint32_t sb = smem_u32(base);

    const int t = threadIdx.x, wid = t >> 5, lane = t & 31;
    const int nt = blockIdx.x, ot = blockIdx.y, b = blockIdx.z;
    const int n0 = nt * 128, o0 = ot * 128;
    const int wm = wid & 3;          // m warp tile (32 rows)
    const int wn = wid >> 2;         // n warp tile (32 cols), 0..3

    // A cp.async mapping: 128 rows x 64B, 4 segs/row, 512 threads -> 1 seg each
    const int ar = t >> 2, aseg = (t & 3);
    const __nv_bfloat16* wha = g_wp_hi + (ll)(o0 + ar) * IN_C + aseg * 8;
    const __nv_bfloat16* wla = g_wp_lo + (ll)(o0 + ar) * IN_C + aseg * 8;
    const uint32_t adst = sb + A_HI + ar * A_STR + aseg * 16;

    // B LDG mapping: 32 k-rows x 128 n, 2 float4/thread
    const int kr = t >> 4, nb = (t & 15) * 8;
    const float* fsrc = feats + ((ll)b * IN_C + kr) * HW + n0 + nb;
    const uint32_t bdst = sb + B_HI + kr * B_STR + nb * 2;

    // stage preds row (epilogue)
    if (t < 128) ((float*)(base + PREDS))[t] = preds[(ll)b * HW + n0 + t];

    float d[2][4][4];
#pragma unroll
    for (int i = 0; i < 2; i++)
#pragma unroll
        for (int j = 0; j < 4; j++)
#pragma unroll
            for (int k = 0; k < 4; k++) d[i][j][k] = 0.0f;

    float4 bR0, bR1;

    // ---- prologue: chunk 0 ----
    bR0 = *(const float4*)(fsrc);
    bR1 = *(const float4*)(fsrc + 4);
    cpasync16(adst,              wha);
    cpasync16(adst + (A_LO - A_HI), wla);
    CP_COMMIT();
    {
        uint2 h0, l0, h1, l1;
        split4(bR0, h0, l0); split4(bR1, h1, l1);
        *(uint4*)(base + (bdst - sb))                 = make_uint4(h0.x, h0.y, h1.x, h1.y);
        *(uint4*)(base + (bdst - sb) + (B_LO - B_HI)) = make_uint4(l0.x, l0.y, l1.x, l1.y);
    }
    CP_WAIT0();
    __syncthreads();

    for (int c = 0; c < NCHUNK; c++) {
        // issue next chunk's loads
        if (c + 1 < NCHUNK) {
            const ll ko = (ll)(c + 1) * KC;
            bR0 = *(const float4*)(fsrc + ko * HW);
            bR1 = *(const float4*)(fsrc + ko * HW + 4);
            const uint32_t db = ((c + 1) & 1) * BUF;
            cpasync16(adst + db,                 wha + ko);
            cpasync16(adst + db + (A_LO - A_HI), wla + ko);
            CP_COMMIT();
        }

        // ---- compute chunk c ----
        const uint32_t bu = sb + (c & 1) * BUF;
#pragma unroll
        for (int s = 0; s < 2; s++) {
            uint32_t bh[4][2], bl[4][2];
            const int krr = s * 16 + (lane & 15);
#pragma unroll
            for (int nf = 0; nf < 4; nf++) {
                uint32_t ba = bu + B_HI + krr * B_STR + (wn * 32 + nf * 8) * 2;
                ldsm_x2t(bh[nf], ba);
                ldsm_x2t(bl[nf], ba + (B_LO - B_HI));
            }
#pragma unroll
            for (int mf = 0; mf < 2; mf++) {
                const int arr = wm * 32 + mf * 16 + (lane & 15);
                const uint32_t acol = (s * 16 + ((lane >> 4) << 3)) * 2;
                uint32_t aa = bu + A_HI + arr * A_STR + acol;
                uint32_t ah[4], al[4];
                ldsm_x4(ah, aa);
                ldsm_x4(al, aa + (A_LO - A_HI));
#pragma unroll
                for (int nf = 0; nf < 4; nf++) mma_bf16(d[mf][nf], ah, bh[nf]);
#pragma unroll
                for (int nf = 0; nf < 4; nf++) mma_bf16(d[mf][nf], ah, bl[nf]);
#pragma unroll
                for (int nf = 0; nf < 4; nf++) mma_bf16(d[mf][nf], al, bh[nf]);
            }
        }
        __syncthreads();

        // split staged B regs into the next buffer; wait for its A copies
        if (c + 1 < NCHUNK) {
            const uint32_t db = ((c + 1) & 1) * BUF;
            uint2 h0, l0, h1, l1;
            split4(bR0, h0, l0); split4(bR1, h1, l1);
            *(uint4*)(base + (bdst - sb) + db)                 = make_uint4(h0.x, h0.y, h1.x, h1.y);
            *(uint4*)(base + (bdst - sb) + db + (B_LO - B_HI)) = make_uint4(l0.x, l0.y, l1.x, l1.y);
            CP_WAIT0();
        }
        __syncthreads();
    }

    // ---- epilogue ----
    const float* ps = (const float*)(base + PREDS);
    const int r = lane >> 2, cq = lane & 3;
#pragma unroll
    for (int mf = 0; mf < 2; mf++) {
        const int oa = o0 + wm * 32 + mf * 16 + r;
        const int oc = oa + 8;
        const float biasa = bias_p[oa], biasb = bias_p[oc];
        float* xa = out + ((ll)b * 2 * CODE + CODE + oa) * HW + n0;
        float* xc = out + ((ll)b * 2 * CODE + CODE + oc) * HW + n0;
        float ra = 0.0f, rb = 0.0f;
#pragma unroll
        for (int nf = 0; nf < 4; nf++) {
            const int nl = wn * 32 + nf * 8 + cq * 2;
            const float p0 = ps[nl], p1 = ps[nl + 1];
            float v0 = d[mf][nf][0] + biasa, v1 = d[mf][nf][1] + biasa;
            float v2 = d[mf][nf][2] + biasb, v3 = d[mf][nf][3] + biasb;
            ra += v0 * p0 + v1 * p1;
            rb += v2 * p0 + v3 * p1;
            *(float2*)(xa + nl) = make_float2(v0, v1);
            *(float2*)(xc + nl) = make_float2(v2, v3);
        }
        ra += __shfl_xor_sync(0xffffffffu, ra, 1);
        ra += __shfl_xor_sync(0xffffffffu, ra, 2);
        rb += __shfl_xor_sync(0xffffffffu, rb, 1);
        rb += __shfl_xor_sync(0xffffffffu, rb, 2);
        if (cq == 0) {
            g_partial[((ll)b * CODE + oa) * NTP + nt * 4 + wn] = ra;
            g_partial[((ll)b * CODE + oc) * NTP + nt * 4 + wn] = rb;
        }
    }
}

// ===========================================================================
// Kernel 2a: parallel feat reduction, coalesced. 4 threads per 128-float row.
// 8192 rows -> 32 blocks x 1024 threads.
// ===========================================================================
__global__ __launch_bounds__(1024) void feat_reduce_kernel() {
    const int gid = blockIdx.x * 1024 + threadIdx.x;
    const int row = gid >> 2, i = gid & 3;
    const float* p = g_partial + (ll)row * NTP + i * 4;
    float s = 0.0f;
#pragma unroll
    for (int q = 0; q < 8; q++) {
        float4 v = *(const float4*)(p + q * 16);
        s += v.x + v.y + v.z + v.w;
    }
    s += __shfl_xor_sync(0xffffffffu, s, 1);
    s += __shfl_xor_sync(0xffffffffu, s, 2);
    if (i == 0) g_feat[row] = s * (1.0f / HW);
}

// ===========================================================================
// Kernel 2b: sequential EMA scan, fully in shared memory.
// One block, 672 threads (21 warps). smem: queue (80KB) + feats (32KB).
// ===========================================================================
#define SMEM_SCAN ((NCLASSES * MEMN * CODE + BB * CODE + 32) * 4)

__global__ __launch_bounds__(672) void queue_scan_kernel(
    const float* __restrict__ queue_in, const int* __restrict__ labels_raw,
    const int* __restrict__ flag)
{
    extern __shared__ float sm[];
    float* s_q = sm;
    float* s_feat = sm + NCLASSES * MEMN * CODE;
    float* s_logit = s_feat + BB * CODE;
    float* s_fnorm = s_logit + MEMN;

    const int t = threadIdx.x;
    for (int i = t; i < NCLASSES * MEMN * CODE; i += 672) s_q[i] = queue_in[i];
    for (int i = t; i < BB * CODE; i += 672) s_feat[i] = g_feat[i];
    __syncthreads();

    if (*flag == 1) {
        const int warp = t >> 5, lane = t & 31;
        for (int b = 0; b < BB; b++) {
            const int l = get_label(labels_raw, b);
            const float* f = s_feat + b * CODE;

            if (warp < MEMN) {
                const float* slot = s_q + (l * MEMN + warp) * CODE;
                float s = 0.0f;
#pragma unroll
                for (int c = lane; c < CODE; c += 32) s += slot[c] * f[c];
#pragma unroll
                for (int off = 16; off; off >>= 1) s += __shfl_xor_sync(0xffffffffu, s, off);
                if (lane == 0) s_logit[warp] = s;
            } else {
                float s = 0.0f;
#pragma unroll
                for (int c = lane; c < CODE; c += 32) { float v = f[c]; s += v * v; }
#pragma unroll
                for (int off = 16; off; off >>= 1) s += __shfl_xor_sync(0xffffffffu, s, off);
                if (lane == 0) *s_fnorm = sqrtf(s);
            }
            __syncthreads();

            const float fn = *s_fnorm;
            for (int i = t; i < MEMN * CODE; i += 672) {
                const int m = i >> 8, c = i & 255;
                const float lg = s_logit[m];
                const float denom = fmaxf(fabsf(lg) * fn, EPSF);
                const float upd = lg * f[c] / denom;
                float* qp = s_q + (l * MEMN + m) * CODE + c;
                *qp = DECAYF * (*qp) + (1.0f - DECAYF) * upd;
            }
            __syncthreads();
        }
    }

    for (int i = t; i < NCLASSES * MEMN * CODE; i += 672) g_queue[i] = s_q[i];
}

// ===========================================================================
// Kernel 3: memory attention. Grid (HW/512, B) = 256 blocks, 128 threads.
// 4 n per thread (float4 accs), LDS.128 broadcast over c-quads.
// ===========================================================================
__global__ __launch_bounds__(128) void attn_kernel(
    const int* __restrict__ labels_raw, float* __restrict__ out)
{
    const int b = blockIdx.y, n0 = blockIdx.x * 512, t = threadIdx.x;

    __shared__ float sq[MEMN][CODE];
    const int l = get_label(labels_raw, b);
    const float* qsrc = g_queue + (ll)l * MEMN * CODE;
    for (int i = t * 4; i < MEMN * CODE; i += 512)
        *(float4*)(&sq[0][0] + i) = *(const float4*)(qsrc + i);
    __syncthreads();

    const float* xb = out + ((ll)b * 2 * CODE + CODE) * HW;
    float* ob = out + ((ll)b * 2 * CODE) * HW;
    const int j = n0 + t * 4;

    float4 a[MEMN];
#pragma unroll
    for (int m = 0; m < MEMN; m++) a[m] = make_float4(0.f, 0.f, 0.f, 0.f);

#pragma unroll 1
    for (int cqd = 0; cqd < 64; cqd++) {
        const float* xp = xb + (ll)cqd * 4 * HW + j;
        float4 x0 = *(const float4*)(xp);
        float4 x1 = *(const float4*)(xp + HW);
        float4 x2 = *(const float4*)(xp + 2 * HW);
        float4 x3 = *(const float4*)(xp + 3 * HW);
#pragma unroll
        for (int m = 0; m < MEMN; m++) {
            float4 qv = *(const float4*)&sq[m][cqd * 4];
            a[m].x += qv.x * x0.x + qv.y * x1.x + qv.z * x2.x + qv.w * x3.x;
            a[m].y += qv.x * x0.y + qv.y * x1.y + qv.z * x2.y + qv.w * x3.y;
            a[m].z += qv.x * x0.z + qv.y * x1.z + qv.z * x2.z + qv.w * x3.z;
            a[m].w += qv.x * x0.w + qv.y * x1.w + qv.z * x2.w + qv.w * x3.w;
        }
    }

    // softmax over m, per n lane, in registers
    float4 mx = a[0];
#pragma unroll
    for (int m = 1; m < MEMN; m++) {
        mx.x = fmaxf(mx.x, a[m].x); mx.y = fmaxf(mx.y, a[m].y);
        mx.z = fmaxf(mx.z, a[m].z); mx.w = fmaxf(mx.w, a[m].w);
    }
    float4 s = make_float4(0.f, 0.f, 0.f, 0.f);
#pragma unroll
    for (int m = 0; m < MEMN; m++) {
        a[m].x = expf(a[m].x - mx.x); s.x += a[m].x;
        a[m].y = expf(a[m].y - mx.y); s.y += a[m].y;
        a[m].z = expf(a[m].z - mx.z); s.z += a[m].z;
        a[m].w = expf(a[m].w - mx.w); s.w += a[m].w;
    }
    const float4 inv = make_float4(1.f / s.x, 1.f / s.y, 1.f / s.z, 1.f / s.w);
#pragma unroll
    for (int m = 0; m < MEMN; m++) {
        a[m].x *= inv.x; a[m].y *= inv.y; a[m].z *= inv.z; a[m].w *= inv.w;
    }

    // new_feat[c][j..j+3] = sum_m q[m][c] * attn[m]
#pragma unroll 1
    for (int cqd = 0; cqd < 64; cqd++) {
        float4 o0 = make_float4(0.f, 0.f, 0.f, 0.f);
        float4 o1 = make_float4(0.f, 0.f, 0.f, 0.f);
        float4 o2 = make_float4(0.f, 0.f, 0.f, 0.f);
        float4 o3 = make_float4(0.f, 0.f, 0.f, 0.f);
#pragma unroll
        for (int m = 0; m < MEMN; m++) {
            float4 qv = *(const float4*)&sq[m][cqd * 4];
            o0.x += qv.x * a[m].x; o0.y += qv.x * a[m].y; o0.z += qv.x * a[m].z; o0.w += qv.x * a[m].w;
            o1.x += qv.y * a[m].x; o1.y += qv.y * a[m].y; o1.z += qv.y * a[m].z; o1.w += qv.y * a[m].w;
            o2.x += qv.z * a[m].x; o2.y += qv.z * a[m].y; o2.z += qv.z * a[m].z; o2.w += qv.z * a[m].w;
            o3.x += qv.w * a[m].x; o3.y += qv.w * a[m].y; o3.z += qv.w * a[m].z; o3.w += qv.w * a[m].w;
        }
        float* op = ob + (ll)cqd * 4 * HW + j;
        *(float4*)(op)          = o0;
        *(float4*)(op + HW)     = o1;
        *(float4*)(op + 2 * HW) = o2;
        *(float4*)(op + 3 * HW) = o3;
    }
}

// ---------------------------------------------------------------------------
extern "C" void kernel_launch(void* const* d_in, const int* in_sizes, int n_in,
                              void* d_out, int out_size) {
    const float* feats  = (const float*)d_in[0];
    const float* preds  = (const float*)d_in[1];
    const int*   labels = (const int*)  d_in[2];
    const int*   flag   = (const int*)  d_in[3];
    const float* queue  = (const float*)d_in[4];
    const float* Wp     = (const float*)d_in[5];
    const float* bp     = (const float*)d_in[6];
    float* out = (float*)d_out;

    cudaFuncSetAttribute(gemm_proj_mma,
                         cudaFuncAttributeMaxDynamicSharedMemorySize, SMEM_GEMM);
    cudaFuncSetAttribute(queue_scan_kernel,
                         cudaFuncAttributeMaxDynamicSharedMemorySize, SMEM_SCAN);

    convert_wp<<<CODE * IN_C / 1024, 256>>>(Wp);

    dim3 g1(HW / 128, CODE / 128, BB);
    gemm_proj_mma<<<g1, 512, SMEM_GEMM>>>(feats, preds, bp, out);

    feat_reduce_kernel<<<BB, 1024>>>();
    queue_scan_kernel<<<1, 672, SMEM_SCAN>>>(queue, labels, flag);

    dim3 g3(HW / 512, BB);
    attn_kernel<<<g3, 128>>>(labels, out);
}

// round 9
// speedup vs baseline: 2.3390x; 1.1802x over previous
#include <cuda_runtime.h>
#include <cuda_bf16.h>
#include <cstdint>

#define BB 32
#define IN_C 512
#define HW 4096
#define CODE 256
#define NCLASSES 4
#define MEMN 20
#define DECAYF 0.9f
#define EPSF 1e-12f
#define NTP 128            // partials per (b,o): 32 n-tiles x 4 wn quarters

typedef long long ll;

// Deterministic scratch (no atomics anywhere).
__device__ float g_partial[BB * CODE * NTP];
__device__ float g_feat[BB * CODE];
__device__ float g_queue[NCLASSES * MEMN * CODE];

// Pre-converted bf16 hi/lo of Wp only (tiny).
__device__ __nv_bfloat16 g_wp_hi[CODE * IN_C];
__device__ __nv_bfloat16 g_wp_lo[CODE * IN_C];

// ---------------------------------------------------------------------------
// helpers
// ---------------------------------------------------------------------------
__device__ __forceinline__ uint32_t smem_u32(const void* p) {
    uint32_t a;
    asm("{ .reg .u64 t; cvta.to.shared.u64 t, %1; cvt.u32.u64 %0, t; }" : "=r"(a) : "l"(p));
    return a;
}
__device__ __forceinline__ void ldsm_x4(uint32_t a[4], uint32_t addr) {
    asm volatile("ldmatrix.sync.aligned.m8n8.x4.shared.b16 {%0,%1,%2,%3}, [%4];"
                 : "=r"(a[0]), "=r"(a[1]), "=r"(a[2]), "=r"(a[3]) : "r"(addr));
}
__device__ __forceinline__ void ldsm_x2t(uint32_t b[2], uint32_t addr) {
    asm volatile("ldmatrix.sync.aligned.m8n8.x2.trans.shared.b16 {%0,%1}, [%2];"
                 : "=r"(b[0]), "=r"(b[1]) : "r"(addr));
}
__device__ __forceinline__ void mma_bf16(float d[4], const uint32_t a[4], const uint32_t b[2]) {
    asm volatile("mma.sync.aligned.m16n8k16.row.col.f32.bf16.bf16.f32 "
                 "{%0,%1,%2,%3}, {%4,%5,%6,%7}, {%8,%9}, {%0,%1,%2,%3};"
                 : "+f"(d[0]), "+f"(d[1]), "+f"(d[2]), "+f"(d[3])
                 : "r"(a[0]), "r"(a[1]), "r"(a[2]), "r"(a[3]), "r"(b[0]), "r"(b[1]));
}
__device__ __forceinline__ void cpasync16(uint32_t dst, const void* src) {
    asm volatile("cp.async.cg.shared.global [%0], [%1], 16;" :: "r"(dst), "l"(src));
}
#define CP_COMMIT() asm volatile("cp.async.commit_group;" ::: "memory")
#define CP_WAIT0()  asm volatile("cp.async.wait_group 0;" ::: "memory")

// bf16 hi/lo split of a float4, packed 4xbf16 -> uint2
__device__ __forceinline__ void split4(float4 v, uint2& hi, uint2& lo) {
    __nv_bfloat16 h0 = __float2bfloat16_rn(v.x), h1 = __float2bfloat16_rn(v.y);
    __nv_bfloat16 h2 = __float2bfloat16_rn(v.z), h3 = __float2bfloat16_rn(v.w);
    float r0 = v.x - __bfloat162float(h0), r1 = v.y - __bfloat162float(h1);
    float r2 = v.z - __bfloat162float(h2), r3 = v.w - __bfloat162float(h3);
    __nv_bfloat16 l0 = __float2bfloat16_rn(r0), l1 = __float2bfloat16_rn(r1);
    __nv_bfloat16 l2 = __float2bfloat16_rn(r2), l3 = __float2bfloat16_rn(r3);
    hi.x = (uint32_t)__bfloat16_as_ushort(h0) | ((uint32_t)__bfloat16_as_ushort(h1) << 16);
    hi.y = (uint32_t)__bfloat16_as_ushort(h2) | ((uint32_t)__bfloat16_as_ushort(h3) << 16);
    lo.x = (uint32_t)__bfloat16_as_ushort(l0) | ((uint32_t)__bfloat16_as_ushort(l1) << 16);
    lo.y = (uint32_t)__bfloat16_as_ushort(l2) | ((uint32_t)__bfloat16_as_ushort(l3) << 16);
}

// labels may be int32 or int64; detect on device (int64 -> odd words all zero).
__device__ __forceinline__ int get_label(const int* lab, int i) {
    bool odd_zero = true;
#pragma unroll
    for (int k = 1; k < 32; k += 2) odd_zero &= (lab[k] == 0);
    return odd_zero ? lab[2 * i] : lab[i];
}

// ===========================================================================
// Kernel 0: Wp fp32 -> bf16 hi/lo (131072 elems, trivial).
// ===========================================================================
__global__ __launch_bounds__(256) void convert_wp(const float* __restrict__ Wp) {
    const int i = (blockIdx.x * 256 + threadIdx.x) * 4;
    float4 v = *(const float4*)(Wp + i);
    uint2 hi, lo; split4(v, hi, lo);
    *(uint2*)(g_wp_hi + i) = hi;
    *(uint2*)(g_wp_lo + i) = lo;
}

// ===========================================================================
// Kernel 1: HMMA bf16-split GEMM, fused B conversion, M=256 CTA tile.
// Per CTA: ALL 256 o x 128 n, K=512 in 16 chunks of 32 -> feats read ONCE.
// 512 threads, 16 warps (4m x 4n), warp tile 64x32. 3-split, fp32 acc.
// A (Wp bf16 pre-split) via cp.async; B (feats fp32) LDG->regs->split->STS.
// ===========================================================================
#define KC 32
#define NCHUNK 16
// A tile: [256 o][KC k] bf16, row stride 80 B  -> 20480 B per region
// B tile: [KC k][128 n] bf16, row stride 272 B -> 8704 B per region
#define A_STR 80
#define B_STR 272
#define A_HI 0
#define A_LO 20480
#define B_HI 40960
#define B_LO 49664
#define BUF 58368
#define PREDS (2 * BUF)
#define SMEM_GEMM (PREDS + 512 + 16)

__global__ __launch_bounds__(512, 1) void gemm_proj_mma(
    const float* __restrict__ feats, const float* __restrict__ preds,
    const float* __restrict__ bias_p, float* __restrict__ out)
{
    extern __shared__ char base[];
    const uint32_t sb = smem_u32(base);

    const int t = threadIdx.x, wid = t >> 5, lane = t & 31;
    const int nt = blockIdx.x, b = blockIdx.y;
    const int n0 = nt * 128;
    const int wm = wid & 3;          // m warp tile (64 rows)
    const int wn = wid >> 2;         // n warp tile (32 cols)

    // A cp.async mapping: 256 rows x 4 segs(16B) per region, 512 thr -> 2 segs
    const int ar = t >> 1, as0 = (t & 1) * 2;
    const __nv_bfloat16* wha = g_wp_hi + (ll)ar * IN_C + as0 * 8;
    const __nv_bfloat16* wla = g_wp_lo + (ll)ar * IN_C + as0 * 8;
    const uint32_t adst = sb + A_HI + ar * A_STR + as0 * 16;

    // B LDG mapping: 32 k-rows x 128 n fp32, 2 float4/thread
    const int kr = t >> 4, nb = (t & 15) * 8;
    const float* fsrc = feats + ((ll)b * IN_C + kr) * HW + n0 + nb;
    const uint32_t bdst = sb + B_HI + kr * B_STR + nb * 2;

    // stage preds row (epilogue)
    if (t < 128) ((float*)(base + PREDS))[t] = preds[(ll)b * HW + n0 + t];

    float d[4][4][4];
#pragma unroll
    for (int i = 0; i < 4; i++)
#pragma unroll
        for (int j = 0; j < 4; j++)
#pragma unroll
            for (int k = 0; k < 4; k++) d[i][j][k] = 0.0f;

    float4 bR0, bR1;

    // ---- prologue: chunk 0 ----
    bR0 = *(const float4*)(fsrc);
    bR1 = *(const float4*)(fsrc + 4);
    cpasync16(adst,                      wha);
    cpasync16(adst + 16,                 wha + 8);
    cpasync16(adst + (A_LO - A_HI),      wla);
    cpasync16(adst + (A_LO - A_HI) + 16, wla + 8);
    CP_COMMIT();
    {
        uint2 h0, l0, h1, l1;
        split4(bR0, h0, l0); split4(bR1, h1, l1);
        *(uint4*)(base + (bdst - sb))                 = make_uint4(h0.x, h0.y, h1.x, h1.y);
        *(uint4*)(base + (bdst - sb) + (B_LO - B_HI)) = make_uint4(l0.x, l0.y, l1.x, l1.y);
    }
    CP_WAIT0();
    __syncthreads();

    for (int c = 0; c < NCHUNK; c++) {
        // issue next chunk's loads
        if (c + 1 < NCHUNK) {
            const ll ko = (ll)(c + 1) * KC;
            bR0 = *(const float4*)(fsrc + ko * HW);
            bR1 = *(const float4*)(fsrc + ko * HW + 4);
            const uint32_t db = ((c + 1) & 1) * BUF;
            cpasync16(adst + db,                      wha + ko);
            cpasync16(adst + db + 16,                 wha + ko + 8);
            cpasync16(adst + db + (A_LO - A_HI),      wla + ko);
            cpasync16(adst + db + (A_LO - A_HI) + 16, wla + ko + 8);
            CP_COMMIT();
        }

        // ---- compute chunk c ----
        const uint32_t bu = sb + (c & 1) * BUF;
#pragma unroll
        for (int s = 0; s < 2; s++) {
            uint32_t bh[4][2], bl[4][2];
            const int krr = s * 16 + (lane & 15);
#pragma unroll
            for (int nf = 0; nf < 4; nf++) {
                uint32_t ba = bu + B_HI + krr * B_STR + (wn * 32 + nf * 8) * 2;
                ldsm_x2t(bh[nf], ba);
                ldsm_x2t(bl[nf], ba + (B_LO - B_HI));
            }
#pragma unroll
            for (int mf = 0; mf < 4; mf++) {
                const int arr = wm * 64 + mf * 16 + (lane & 15);
                const uint32_t acol = (s * 16 + ((lane >> 4) << 3)) * 2;
                uint32_t aa = bu + A_HI + arr * A_STR + acol;
                uint32_t ah[4], al[4];
                ldsm_x4(ah, aa);
                ldsm_x4(al, aa + (A_LO - A_HI));
#pragma unroll
                for (int nf = 0; nf < 4; nf++) mma_bf16(d[mf][nf], ah, bh[nf]);
#pragma unroll
                for (int nf = 0; nf < 4; nf++) mma_bf16(d[mf][nf], ah, bl[nf]);
#pragma unroll
                for (int nf = 0; nf < 4; nf++) mma_bf16(d[mf][nf], al, bh[nf]);
            }
        }
        __syncthreads();

        // split staged B regs into the next buffer; wait for its A copies
        if (c + 1 < NCHUNK) {
            const uint32_t db = ((c + 1) & 1) * BUF;
            uint2 h0, l0, h1, l1;
            split4(bR0, h0, l0); split4(bR1, h1, l1);
            *(uint4*)(base + (bdst - sb) + db)                 = make_uint4(h0.x, h0.y, h1.x, h1.y);
            *(uint4*)(base + (bdst - sb) + db + (B_LO - B_HI)) = make_uint4(l0.x, l0.y, l1.x, l1.y);
            CP_WAIT0();
        }
        __syncthreads();
    }

    // ---- epilogue ----
    const float* ps = (const float*)(base + PREDS);
    const int r = lane >> 2, cq = lane & 3;
#pragma unroll
    for (int mf = 0; mf < 4; mf++) {
        const int oa = wm * 64 + mf * 16 + r;
        const int oc = oa + 8;
        const float biasa = bias_p[oa], biasb = bias_p[oc];
        float* xa = out + ((ll)b * 2 * CODE + CODE + oa) * HW + n0;
        float* xc = out + ((ll)b * 2 * CODE + CODE + oc) * HW + n0;
        float ra = 0.0f, rb = 0.0f;
#pragma unroll
        for (int nf = 0; nf < 4; nf++) {
            const int nl = wn * 32 + nf * 8 + cq * 2;
            const float p0 = ps[nl], p1 = ps[nl + 1];
            float v0 = d[mf][nf][0] + biasa, v1 = d[mf][nf][1] + biasa;
            float v2 = d[mf][nf][2] + biasb, v3 = d[mf][nf][3] + biasb;
            ra += v0 * p0 + v1 * p1;
            rb += v2 * p0 + v3 * p1;
            *(float2*)(xa + nl) = make_float2(v0, v1);
            *(float2*)(xc + nl) = make_float2(v2, v3);
        }
        ra += __shfl_xor_sync(0xffffffffu, ra, 1);
        ra += __shfl_xor_sync(0xffffffffu, ra, 2);
        rb += __shfl_xor_sync(0xffffffffu, rb, 1);
        rb += __shfl_xor_sync(0xffffffffu, rb, 2);
        if (cq == 0) {
            g_partial[((ll)b * CODE + oa) * NTP + nt * 4 + wn] = ra;
            g_partial[((ll)b * CODE + oc) * NTP + nt * 4 + wn] = rb;
        }
    }
}

// ===========================================================================
// Kernel 2a: parallel feat reduction, coalesced. 4 threads per 128-float row.
// ===========================================================================
__global__ __launch_bounds__(1024) void feat_reduce_kernel() {
    const int gid = blockIdx.x * 1024 + threadIdx.x;
    const int row = gid >> 2, i = gid & 3;
    const float* p = g_partial + (ll)row * NTP + i * 4;
    float s = 0.0f;
#pragma unroll
    for (int q = 0; q < 8; q++) {
        float4 v = *(const float4*)(p + q * 16);
        s += v.x + v.y + v.z + v.w;
    }
    s += __shfl_xor_sync(0xffffffffu, s, 1);
    s += __shfl_xor_sync(0xffffffffu, s, 2);
    if (i == 0) g_feat[row] = s * (1.0f / HW);
}

// ===========================================================================
// Kernel 2b: sequential EMA scan, fully in shared memory.
// Division hoisted: coef[m] = (1-decay)*lg/denom (20 divs/step, not 5120).
// ===========================================================================
#define SMEM_SCAN ((NCLASSES * MEMN * CODE + BB * CODE + 64) * 4)

__global__ __launch_bounds__(672) void queue_scan_kernel(
    const float* __restrict__ queue_in, const int* __restrict__ labels_raw,
    const int* __restrict__ flag)
{
    extern __shared__ float sm[];
    float* s_q = sm;
    float* s_feat = sm + NCLASSES * MEMN * CODE;
    float* s_logit = s_feat + BB * CODE;     // 20
    float* s_fnorm = s_logit + MEMN;         // 1
    float* s_coef  = s_fnorm + 1;            // 20

    const int t = threadIdx.x;
    for (int i = t; i < NCLASSES * MEMN * CODE; i += 672) s_q[i] = queue_in[i];
    for (int i = t; i < BB * CODE; i += 672) s_feat[i] = g_feat[i];
    __syncthreads();

    if (*flag == 1) {
        const int warp = t >> 5, lane = t & 31;
        for (int b = 0; b < BB; b++) {
            const int l = get_label(labels_raw, b);
            const float* f = s_feat + b * CODE;

            if (warp < MEMN) {
                const float* slot = s_q + (l * MEMN + warp) * CODE;
                float s = 0.0f;
#pragma unroll
                for (int c = lane; c < CODE; c += 32) s += slot[c] * f[c];
#pragma unroll
                for (int off = 16; off; off >>= 1) s += __shfl_xor_sync(0xffffffffu, s, off);
                if (lane == 0) s_logit[warp] = s;
            } else {
                float s = 0.0f;
#pragma unroll
                for (int c = lane; c < CODE; c += 32) { float v = f[c]; s += v * v; }
#pragma unroll
                for (int off = 16; off; off >>= 1) s += __shfl_xor_sync(0xffffffffu, s, off);
                if (lane == 0) *s_fnorm = sqrtf(s);
            }
            __syncthreads();

            if (t < MEMN) {
                const float lg = s_logit[t];
                const float denom = fmaxf(fabsf(lg) * (*s_fnorm), EPSF);
                s_coef[t] = (1.0f - DECAYF) * lg / denom;
            }
            __syncthreads();

            for (int i = t; i < MEMN * CODE; i += 672) {
                const int m = i >> 8, c = i & 255;
                float* qp = s_q + (l * MEMN + m) * CODE + c;
                *qp = DECAYF * (*qp) + s_coef[m] * f[c];
            }
            __syncthreads();
        }
    }

    for (int i = t; i < NCLASSES * MEMN * CODE; i += 672) g_queue[i] = s_q[i];
}

// ===========================================================================
// Kernel 3: memory attention. Grid (HW/256, B) = 512 blocks, 128 threads.
// 2 n per thread -> 64K threads chip-wide (~14 warps/SM).
// ===========================================================================
__global__ __launch_bounds__(128) void attn_kernel(
    const int* __restrict__ labels_raw, float* __restrict__ out)
{
    const int b = blockIdx.y, n0 = blockIdx.x * 256, t = threadIdx.x;

    __shared__ float sq[MEMN][CODE];
    const int l = get_label(labels_raw, b);
    const float* qsrc = g_queue + (ll)l * MEMN * CODE;
    for (int i = t * 4; i < MEMN * CODE; i += 512)
        *(float4*)(&sq[0][0] + i) = *(const float4*)(qsrc + i);
    __syncthreads();

    const float* xb = out + ((ll)b * 2 * CODE + CODE) * HW;
    float* ob = out + ((ll)b * 2 * CODE) * HW;
    const int j = n0 + t * 2;

    float a0[MEMN], a1[MEMN];
#pragma unroll
    for (int m = 0; m < MEMN; m++) { a0[m] = 0.f; a1[m] = 0.f; }

#pragma unroll 1
    for (int cqd = 0; cqd < 64; cqd++) {
        const float* xp = xb + (ll)cqd * 4 * HW + j;
        float2 x0 = *(const float2*)(xp);
        float2 x1 = *(const float2*)(xp + HW);
        float2 x2 = *(const float2*)(xp + 2 * HW);
        float2 x3 = *(const float2*)(xp + 3 * HW);
#pragma unroll
        for (int m = 0; m < MEMN; m++) {
            float4 qv = *(const float4*)&sq[m][cqd * 4];
            a0[m] += qv.x * x0.x + qv.y * x1.x + qv.z * x2.x + qv.w * x3.x;
            a1[m] += qv.x * x0.y + qv.y * x1.y + qv.z * x2.y + qv.w * x3.y;
        }
    }

    float m0 = a0[0], m1 = a1[0];
#pragma unroll
    for (int m = 1; m < MEMN; m++) { m0 = fmaxf(m0, a0[m]); m1 = fmaxf(m1, a1[m]); }
    float s0 = 0.f, s1 = 0.f;
#pragma unroll
    for (int m = 0; m < MEMN; m++) {
        a0[m] = __expf(a0[m] - m0); s0 += a0[m];
        a1[m] = __expf(a1[m] - m1); s1 += a1[m];
    }
    const float i0 = 1.f / s0, i1 = 1.f / s1;
#pragma unroll
    for (int m = 0; m < MEMN; m++) { a0[m] *= i0; a1[m] *= i1; }

#pragma unroll 1
    for (int cqd = 0; cqd < 64; cqd++) {
        float o0x = 0.f, o0y = 0.f, o1x = 0.f, o1y = 0.f;
        float o2x = 0.f, o2y = 0.f, o3x = 0.f, o3y = 0.f;
#pragma unroll
        for (int m = 0; m < MEMN; m++) {
            float4 qv = *(const float4*)&sq[m][cqd * 4];
            o0x += qv.x * a0[m]; o0y += qv.x * a1[m];
            o1x += qv.y * a0[m]; o1y += qv.y * a1[m];
            o2x += qv.z * a0[m]; o2y += qv.z * a1[m];
            o3x += qv.w * a0[m]; o3y += qv.w * a1[m];
        }
        float* op = ob + (ll)cqd * 4 * HW + j;
        *(float2*)(op)          = make_float2(o0x, o0y);
        *(float2*)(op + HW)     = make_float2(o1x, o1y);
        *(float2*)(op + 2 * HW) = make_float2(o2x, o2y);
        *(float2*)(op + 3 * HW) = make_float2(o3x, o3y);
    }
}

// ---------------------------------------------------------------------------
extern "C" void kernel_launch(void* const* d_in, const int* in_sizes, int n_in,
                              void* d_out, int out_size) {
    const float* feats  = (const float*)d_in[0];
    const float* preds  = (const float*)d_in[1];
    const int*   labels = (const int*)  d_in[2];
    const int*   flag   = (const int*)  d_in[3];
    const float* queue  = (const float*)d_in[4];
    const float* Wp     = (const float*)d_in[5];
    const float* bp     = (const float*)d_in[6];
    float* out = (float*)d_out;

    cudaFuncSetAttribute(gemm_proj_mma,
                         cudaFuncAttributeMaxDynamicSharedMemorySize, SMEM_GEMM);
    cudaFuncSetAttribute(queue_scan_kernel,
                         cudaFuncAttributeMaxDynamicSharedMemorySize, SMEM_SCAN);

    convert_wp<<<CODE * IN_C / 1024, 256>>>(Wp);

    dim3 g1(HW / 128, BB);
    gemm_proj_mma<<<g1, 512, SMEM_GEMM>>>(feats, preds, bp, out);

    feat_reduce_kernel<<<BB, 1024>>>();
    queue_scan_kernel<<<1, 672, SMEM_SCAN>>>(queue, labels, flag);

    dim3 g3(HW / 256, BB);
    attn_kernel<<<g3, 128>>>(labels, out);
}